// round 1
// baseline (speedup 1.0000x reference)
#include <cuda_runtime.h>

// PatchChamferDistance: B=32, G=64, P=256, D=3  (fp32)
// per patch: dist2[i][j] = max(|p_i|^2 + |q_j|^2 - 2 p_i.q_j, 0)
// out = mean_patch( mean_i min_j dist2 + mean_j min_i dist2 )

#define BGQ   2048   // 32*64 patches
#define NP    256    // points per patch

__global__ void pcd_zero_kernel(float* out) { out[0] = 0.0f; }

__global__ __launch_bounds__(NP, 8)
void pcd_chamfer_kernel(const float* __restrict__ pred,
                        const float* __restrict__ tgt,
                        float* __restrict__ out)
{
    __shared__ float4 sp[NP];   // pred points: x,y,z,|p|^2
    __shared__ float4 sq[NP];   // tgt  points: x,y,z,|q|^2

    const int patch = blockIdx.x;
    const int t     = threadIdx.x;

    const float* pb = pred + (size_t)patch * NP * 3;
    const float* qb = tgt  + (size_t)patch * NP * 3;

    // cooperative load: thread t loads point t of each cloud
    {
        float x = pb[t * 3 + 0];
        float y = pb[t * 3 + 1];
        float z = pb[t * 3 + 2];
        sp[t] = make_float4(x, y, z, x * x + y * y + z * z);
        x = qb[t * 3 + 0];
        y = qb[t * 3 + 1];
        z = qb[t * 3 + 2];
        sq[t] = make_float4(x, y, z, x * x + y * y + z * z);
    }
    __syncthreads();

    // ---- forward pass: thread t owns pred point t, scan all targets ----
    float4 p = sp[t];
    float fmin = 3.402823e38f;
#pragma unroll 16
    for (int j = 0; j < NP; j++) {
        float4 q = sq[j];                       // warp-uniform addr -> LDS broadcast
        float dot = p.x * q.x;
        dot = fmaf(p.y, q.y, dot);
        dot = fmaf(p.z, q.z, dot);
        float d = fmaf(-2.0f, dot, p.w + q.w);
        fmin = fminf(fmin, d);
    }

    // ---- backward pass: thread t owns tgt point t, scan all preds ----
    float4 q0 = sq[t];
    float bmin = 3.402823e38f;
#pragma unroll 16
    for (int j = 0; j < NP; j++) {
        float4 pp = sp[j];                      // warp-uniform addr -> LDS broadcast
        float dot = q0.x * pp.x;
        dot = fmaf(q0.y, pp.y, dot);
        dot = fmaf(q0.z, pp.z, dot);
        float d = fmaf(-2.0f, dot, q0.w + pp.w);
        bmin = fminf(bmin, d);
    }

    // clamp commutes with min: min_j max(d,0) == max(min_j d, 0)
    float v = fmaxf(fmin, 0.0f) + fmaxf(bmin, 0.0f);

    // ---- block reduction (sum of 256 values) ----
#pragma unroll
    for (int o = 16; o > 0; o >>= 1)
        v += __shfl_down_sync(0xffffffffu, v, o);

    __shared__ float wsum[NP / 32];
    if ((t & 31) == 0) wsum[t >> 5] = v;
    __syncthreads();

    if (t < (NP / 32)) {
        float s = wsum[t];
#pragma unroll
        for (int o = (NP / 64); o > 0; o >>= 1)
            s += __shfl_down_sync(0x000000ffu, s, o);
        if (t == 0) {
            // per-patch mean over NP, then mean over BGQ patches
            atomicAdd(out, s * (1.0f / ((float)NP * (float)BGQ)));
        }
    }
}

extern "C" void kernel_launch(void* const* d_in, const int* in_sizes, int n_in,
                              void* d_out, int out_size)
{
    const float* pred = (const float*)d_in[0];
    const float* tgt  = (const float*)d_in[1];
    float* out = (float*)d_out;

    pcd_zero_kernel<<<1, 1>>>(out);
    pcd_chamfer_kernel<<<BGQ, NP>>>(pred, tgt, out);
}